// round 2
// baseline (speedup 1.0000x reference)
#include <cuda_runtime.h>

#define N_USERS 200000
#define N_SPOTS 50000
#define D 64
#define DV 16  // D/4 float4 per row

// Scratch (no allocations allowed): degrees + inv-sqrt per node.
__device__ float g_deg_user[N_USERS];
__device__ float g_deg_spot[N_SPOTS];
__device__ float g_inv_user[N_USERS];
__device__ float g_inv_spot[N_SPOTS];

__device__ __forceinline__ void red_add_v4(float4* addr, float4 v) {
    asm volatile("red.global.add.v4.f32 [%0], {%1, %2, %3, %4};"
                 :: "l"(addr), "f"(v.x), "f"(v.y), "f"(v.z), "f"(v.w)
                 : "memory");
}

// Zero output buffer and degree scratch.
__global__ void zero_kernel(float4* out, int n_out4) {
    int stride = gridDim.x * blockDim.x;
    int i = blockIdx.x * blockDim.x + threadIdx.x;
    float4 z = make_float4(0.f, 0.f, 0.f, 0.f);
    for (int j = i; j < n_out4; j += stride) out[j] = z;
    for (int j = i; j < N_USERS; j += stride) g_deg_user[j] = 0.f;
    for (int j = i; j < N_SPOTS; j += stride) g_deg_spot[j] = 0.f;
}

// Per-edge degree counting.
__global__ void degree_kernel(const int* __restrict__ ui,
                              const int* __restrict__ si, int E) {
    int e = blockIdx.x * blockDim.x + threadIdx.x;
    if (e < E) {
        atomicAdd(&g_deg_user[ui[e]], 1.0f);
        atomicAdd(&g_deg_spot[si[e]], 1.0f);
    }
}

// inv_sqrt of degrees (isolated nodes -> rsqrt(1e-6)).
__global__ void rsqrt_kernel() {
    int i = blockIdx.x * blockDim.x + threadIdx.x;
    if (i < N_USERS) {
        float d = g_deg_user[i];
        g_inv_user[i] = rsqrtf(d == 0.f ? 1e-6f : d);
    }
    if (i < N_SPOTS) {
        float d = g_deg_spot[i];
        g_inv_spot[i] = rsqrtf(d == 0.f ? 1e-6f : d);
    }
}

// Main scatter: 16 threads per edge, one float4 lane each.
// user_out[u] += spot_x[s] * inv_spot[s]
// spot_out[s] += user_x[u] * inv_user[u]
__global__ void scatter_kernel(const float4* __restrict__ ux,
                               const float4* __restrict__ sx,
                               const int* __restrict__ ui,
                               const int* __restrict__ si,
                               float4* __restrict__ out_user,
                               float4* __restrict__ out_spot,
                               int E) {
    long long t = (long long)blockIdx.x * blockDim.x + threadIdx.x;
    int e = (int)(t >> 4);
    int lane = (int)(t & 15);
    if (e >= E) return;

    int u = __ldg(&ui[e]);
    int s = __ldg(&si[e]);
    float inv_s = g_inv_spot[s];
    float inv_u = g_inv_user[u];

    float4 sv = __ldg(&sx[s * DV + lane]);
    sv.x *= inv_s; sv.y *= inv_s; sv.z *= inv_s; sv.w *= inv_s;
    red_add_v4(&out_user[u * DV + lane], sv);

    float4 uv = __ldg(&ux[u * DV + lane]);
    uv.x *= inv_u; uv.y *= inv_u; uv.z *= inv_u; uv.w *= inv_u;
    red_add_v4(&out_spot[s * DV + lane], uv);
}

// Post-scale both outputs by destination inv-sqrt degree.
__global__ void scale_kernel(float4* __restrict__ out_user,
                             float4* __restrict__ out_spot) {
    int i = blockIdx.x * blockDim.x + threadIdx.x;
    const int nU = N_USERS * DV;
    const int nS = N_SPOTS * DV;
    if (i < nU) {
        float m = g_inv_user[i >> 4];
        float4 v = out_user[i];
        v.x *= m; v.y *= m; v.z *= m; v.w *= m;
        out_user[i] = v;
    } else if (i < nU + nS) {
        int j = i - nU;
        float m = g_inv_spot[j >> 4];
        float4 v = out_spot[j];
        v.x *= m; v.y *= m; v.z *= m; v.w *= m;
        out_spot[j] = v;
    }
}

extern "C" void kernel_launch(void* const* d_in, const int* in_sizes, int n_in,
                              void* d_out, int out_size) {
    const float4* ux = (const float4*)d_in[0];   // user_x [N_USERS, D]
    const float4* sx = (const float4*)d_in[1];   // spot_x [N_SPOTS, D]
    const int* ui = (const int*)d_in[2];         // user_idx [E]
    const int* si = (const int*)d_in[3];         // spot_idx [E]
    int E = in_sizes[2];

    float* out = (float*)d_out;
    float4* out_user = (float4*)out;                      // [N_USERS, D]
    float4* out_spot = (float4*)(out + (size_t)N_USERS * D);  // [N_SPOTS, D]

    int n_out4 = out_size / 4;

    zero_kernel<<<2048, 256>>>((float4*)out, n_out4);
    degree_kernel<<<(E + 255) / 256, 256>>>(ui, si, E);
    rsqrt_kernel<<<(N_USERS + 255) / 256, 256>>>();

    long long threads = (long long)E * 16;
    int blocks = (int)((threads + 255) / 256);
    scatter_kernel<<<blocks, 256>>>(ux, sx, ui, si, out_user, out_spot, E);

    int n_scale = (N_USERS + N_SPOTS) * DV;
    scale_kernel<<<(n_scale + 255) / 256, 256>>>(out_user, out_spot);
}

// round 4
// speedup vs baseline: 1.3206x; 1.3206x over previous
#include <cuda_runtime.h>

#define N_USERS 200000
#define N_SPOTS 50000
#define D 64
#define DV 16           // D/4 float4 per row
#define MAX_E 3200000
#define CHUNK 512

// ---------------- __device__ scratch (no allocations allowed) ----------------
__device__ int   g_deg_user[N_USERS];
__device__ int   g_deg_spot[N_SPOTS];
__device__ float g_inv_user[N_USERS];
__device__ float g_inv_spot[N_SPOTS];
__device__ int   g_start_user[N_USERS + 1];
__device__ int   g_start_spot[N_SPOTS + 1];
__device__ int   g_cur_user[N_USERS];
__device__ int   g_cur_spot[N_SPOTS];
__device__ int   g_adj_user[MAX_E];   // spot neighbors grouped by user
__device__ int   g_adj_spot[MAX_E];   // user neighbors grouped by spot
__device__ int   g_csum_user[CHUNK];  // chunk partial sums (<=391 used)
__device__ int   g_csum_spot[CHUNK];  // (<=98 used)
__device__ float4 g_user_xs[N_USERS * DV];  // prescaled user_x
__device__ float4 g_spot_xs[N_SPOTS * DV];  // prescaled spot_x

// ---------------- init: zero degree counters ----------------
__global__ void init_kernel() {
    int stride = gridDim.x * blockDim.x;
    int i = blockIdx.x * blockDim.x + threadIdx.x;
    for (int j = i; j < N_USERS; j += stride) g_deg_user[j] = 0;
    for (int j = i; j < N_SPOTS; j += stride) g_deg_spot[j] = 0;
}

// ---------------- degree count ----------------
__global__ void degree_kernel(const int* __restrict__ ui,
                              const int* __restrict__ si, int E) {
    int e = blockIdx.x * blockDim.x + threadIdx.x;
    if (e < E) {
        atomicAdd(&g_deg_user[ui[e]], 1);
        atomicAdd(&g_deg_spot[si[e]], 1);
    }
}

// ---------------- scan phase 1: per-chunk sums ----------------
__global__ void chunk_sum_kernel(const int* __restrict__ deg,
                                 int* __restrict__ sums, int n) {
    __shared__ int sm[CHUNK];
    int i = blockIdx.x * CHUNK + threadIdx.x;
    sm[threadIdx.x] = (i < n) ? deg[i] : 0;
    __syncthreads();
    for (int off = CHUNK / 2; off > 0; off >>= 1) {
        if (threadIdx.x < off) sm[threadIdx.x] += sm[threadIdx.x + off];
        __syncthreads();
    }
    if (threadIdx.x == 0) sums[blockIdx.x] = sm[0];
}

// ---------------- scan phase 2: exclusive scan of chunk sums (1 block) ----------------
__global__ void scan_sums_kernel(int* __restrict__ sums, int n) {
    __shared__ int sm[CHUNK];
    int t = threadIdx.x;
    int v = (t < n) ? sums[t] : 0;
    sm[t] = v;
    __syncthreads();
    for (int off = 1; off < CHUNK; off <<= 1) {
        int x = (t >= off) ? sm[t - off] : 0;
        __syncthreads();
        sm[t] += x;
        __syncthreads();
    }
    if (t < n) sums[t] = sm[t] - v;  // exclusive
}

// ---------------- scan phase 3: per-chunk exclusive scan + offsets -> start/cursor ----------------
__global__ void chunk_scan_kernel(const int* __restrict__ deg,
                                  const int* __restrict__ chunk_off,
                                  int* __restrict__ start,
                                  int* __restrict__ cursor,
                                  int n, int total) {
    __shared__ int sm[CHUNK];
    int i = blockIdx.x * CHUNK + threadIdx.x;
    int t = threadIdx.x;
    int v = (i < n) ? deg[i] : 0;
    sm[t] = v;
    __syncthreads();
    for (int off = 1; off < CHUNK; off <<= 1) {
        int x = (t >= off) ? sm[t - off] : 0;
        __syncthreads();
        sm[t] += x;
        __syncthreads();
    }
    if (i < n) {
        int ex = chunk_off[blockIdx.x] + sm[t] - v;
        start[i]  = ex;
        cursor[i] = ex;
    }
    if (i == 0) start[n] = total;
}

// ---------------- inv-sqrt degrees ----------------
__global__ void inv_kernel() {
    int i = blockIdx.x * blockDim.x + threadIdx.x;
    if (i < N_USERS) {
        int d = g_deg_user[i];
        g_inv_user[i] = rsqrtf(d ? (float)d : 1e-6f);
    }
    if (i < N_SPOTS) {
        int d = g_deg_spot[i];
        g_inv_spot[i] = rsqrtf(d ? (float)d : 1e-6f);
    }
}

// ---------------- prescale feature tables ----------------
__global__ void prescale_kernel(const float4* __restrict__ ux,
                                const float4* __restrict__ sx) {
    int i = blockIdx.x * blockDim.x + threadIdx.x;
    const int nU = N_USERS * DV;
    const int nS = N_SPOTS * DV;
    if (i < nU) {
        float m = g_inv_user[i >> 4];
        float4 v = ux[i];
        v.x *= m; v.y *= m; v.z *= m; v.w *= m;
        g_user_xs[i] = v;
    } else if (i < nU + nS) {
        int j = i - nU;
        float m = g_inv_spot[j >> 4];
        float4 v = sx[j];
        v.x *= m; v.y *= m; v.z *= m; v.w *= m;
        g_spot_xs[j] = v;
    }
}

// ---------------- fill adjacency ----------------
__global__ void fill_kernel(const int* __restrict__ ui,
                            const int* __restrict__ si, int E) {
    int e = blockIdx.x * blockDim.x + threadIdx.x;
    if (e < E) {
        int u = ui[e], s = si[e];
        int pu = atomicAdd(&g_cur_user[u], 1);
        g_adj_user[pu] = s;
        int ps = atomicAdd(&g_cur_spot[s], 1);
        g_adj_spot[ps] = u;
    }
}

// ---------------- pull: out[node] = inv[node] * sum_{nbr} src_prescaled[nbr] ----------------
// 16 lanes per node; each lane owns one float4 column. Neighbor indices loaded
// coalesced 16 at a time and broadcast via segment shfl.
__global__ void pull_kernel(const float4* __restrict__ src,
                            const int* __restrict__ adj,
                            const int* __restrict__ start,
                            const float* __restrict__ inv,
                            float4* __restrict__ out, int n_nodes) {
    int node = blockIdx.x * (blockDim.x >> 4) + (threadIdx.x >> 4);
    int lane = threadIdx.x & 15;
    if (node >= n_nodes) return;
    int b = start[node];
    int e = start[node + 1];
    unsigned mask = 0xFFFFu << (threadIdx.x & 16);

    float4 acc = make_float4(0.f, 0.f, 0.f, 0.f);
    int base = b;
    // full 16-neighbor batches: fully unrolled for MLP
    for (; base + 16 <= e; base += 16) {
        int idx = __ldg(&adj[base + lane]);
#pragma unroll
        for (int k = 0; k < 16; k++) {
            int s = __shfl_sync(mask, idx, k, 16);
            float4 v = __ldg(&src[s * DV + lane]);
            acc.x += v.x; acc.y += v.y; acc.z += v.z; acc.w += v.w;
        }
    }
    // remainder
    if (base < e) {
        int cnt = e - base;
        int idx = (base + lane < e) ? __ldg(&adj[base + lane]) : 0;
        for (int k = 0; k < cnt; k++) {
            int s = __shfl_sync(mask, idx, k, 16);
            float4 v = __ldg(&src[s * DV + lane]);
            acc.x += v.x; acc.y += v.y; acc.z += v.z; acc.w += v.w;
        }
    }
    float m = inv[node];
    acc.x *= m; acc.y *= m; acc.z *= m; acc.w *= m;
    out[node * DV + lane] = acc;
}

extern "C" void kernel_launch(void* const* d_in, const int* in_sizes, int n_in,
                              void* d_out, int out_size) {
    const float4* ux = (const float4*)d_in[0];   // user_x [N_USERS, D]
    const float4* sx = (const float4*)d_in[1];   // spot_x [N_SPOTS, D]
    const int* ui = (const int*)d_in[2];         // user_idx [E]
    const int* si = (const int*)d_in[3];         // spot_idx [E]
    int E = in_sizes[2];

    float* out = (float*)d_out;
    float4* out_user = (float4*)out;                          // [N_USERS, D]
    float4* out_spot = (float4*)(out + (size_t)N_USERS * D);  // [N_SPOTS, D]

    // device-symbol addresses (host side)
    int *p_deg_u, *p_deg_s, *p_start_u, *p_start_s, *p_cur_u, *p_cur_s;
    int *p_csum_u, *p_csum_s, *p_adj_u, *p_adj_s;
    float *p_inv_u, *p_inv_s;
    float4 *p_uxs, *p_sxs;
    cudaGetSymbolAddress((void**)&p_deg_u, g_deg_user);
    cudaGetSymbolAddress((void**)&p_deg_s, g_deg_spot);
    cudaGetSymbolAddress((void**)&p_start_u, g_start_user);
    cudaGetSymbolAddress((void**)&p_start_s, g_start_spot);
    cudaGetSymbolAddress((void**)&p_cur_u, g_cur_user);
    cudaGetSymbolAddress((void**)&p_cur_s, g_cur_spot);
    cudaGetSymbolAddress((void**)&p_csum_u, g_csum_user);
    cudaGetSymbolAddress((void**)&p_csum_s, g_csum_spot);
    cudaGetSymbolAddress((void**)&p_adj_u, g_adj_user);
    cudaGetSymbolAddress((void**)&p_adj_s, g_adj_spot);
    cudaGetSymbolAddress((void**)&p_inv_u, g_inv_user);
    cudaGetSymbolAddress((void**)&p_inv_s, g_inv_spot);
    cudaGetSymbolAddress((void**)&p_uxs, g_user_xs);
    cudaGetSymbolAddress((void**)&p_sxs, g_spot_xs);

    const int nchunk_u = (N_USERS + CHUNK - 1) / CHUNK;  // 391
    const int nchunk_s = (N_SPOTS + CHUNK - 1) / CHUNK;  // 98

    init_kernel<<<512, 256>>>();
    degree_kernel<<<(E + 255) / 256, 256>>>(ui, si, E);

    // user-side scan
    chunk_sum_kernel<<<nchunk_u, CHUNK>>>(p_deg_u, p_csum_u, N_USERS);
    scan_sums_kernel<<<1, CHUNK>>>(p_csum_u, nchunk_u);
    chunk_scan_kernel<<<nchunk_u, CHUNK>>>(p_deg_u, p_csum_u, p_start_u, p_cur_u,
                                           N_USERS, E);
    // spot-side scan
    chunk_sum_kernel<<<nchunk_s, CHUNK>>>(p_deg_s, p_csum_s, N_SPOTS);
    scan_sums_kernel<<<1, CHUNK>>>(p_csum_s, nchunk_s);
    chunk_scan_kernel<<<nchunk_s, CHUNK>>>(p_deg_s, p_csum_s, p_start_s, p_cur_s,
                                           N_SPOTS, E);

    inv_kernel<<<(N_USERS + 255) / 256, 256>>>();

    const int n_pre = (N_USERS + N_SPOTS) * DV;
    prescale_kernel<<<(n_pre + 255) / 256, 256>>>(ux, sx);

    fill_kernel<<<(E + 255) / 256, 256>>>(ui, si, E);

    // pulls: 16 nodes per 256-thread block
    pull_kernel<<<(N_USERS + 15) / 16, 256>>>(p_sxs, p_adj_u, p_start_u, p_inv_u,
                                              out_user, N_USERS);
    pull_kernel<<<(N_SPOTS + 15) / 16, 256>>>(p_uxs, p_adj_s, p_start_s, p_inv_s,
                                              out_spot, N_SPOTS);
}